// round 13
// baseline (speedup 1.0000x reference)
#include <cuda_runtime.h>
#include <cuda_bf16.h>
#include <cuda_fp16.h>
#include <cstdint>

// Problem shape: x[4096,1024], positive[4096,1024], negative[8192,1024]
#define M_ROWS 4096
#define N_ROWS 8192
#define DIM    1024
#define EPSF   1e-8f
#define QSCALE 25.0f             // int8 quantization scale (x ~ N(0,1))

// GEMM tiling: 128x128 CTA tile, 8 warps as 2(M) x 4(N), warp tile 64x32
#define BM 128
#define BN 128
#define BK 64
#define NK (DIM / BK)            // 16
#define NPART (N_ROWS / BN)      // 64 partials per row
#define LDB 80                   // padded smem row bytes: conflict-free ldmatrix
#define NSTAGE 3
#define A_STAGE (BM * LDB)       // 10240
#define B_STAGE (BN * LDB)       // 10240
#define STAGE (A_STAGE + B_STAGE) // 20480
#define DYN_SMEM (NSTAGE * STAGE) // 61440

// ---------------- scratch (no allocations allowed) ----------------
__device__ uint8_t g_Xq[(size_t)M_ROWS * DIM];    // 4 MB  s8
__device__ uint8_t g_Nq[(size_t)N_ROWS * DIM];    // 8 MB  s8
__device__ float g_rnx[M_ROWS];                    // 1/(S^2 * norm(x))
__device__ float g_sim[M_ROWS];
__device__ float g_rnn[N_ROWS];                    // 1/norm(neg)
__device__ float g_partial[(size_t)M_ROWS * NPART];
__device__ float g_rowloss[M_ROWS];

__device__ __forceinline__ uint32_t smem_u32(const void* p) {
    return (uint32_t)__cvta_generic_to_shared(p);
}

// quantize 4 floats -> 4 s8 bytes (byte0 = v0), saturating
__device__ __forceinline__ uint32_t pack_s8x4(float v0, float v1, float v2, float v3) {
    int a0 = __float2int_rn(v0 * QSCALE);
    int a1 = __float2int_rn(v1 * QSCALE);
    int a2 = __float2int_rn(v2 * QSCALE);
    int a3 = __float2int_rn(v3 * QSCALE);
    uint32_t t, pk;
    asm("cvt.pack.sat.s8.s32.b32 %0, %1, %2, %3;" : "=r"(t)  : "r"(a3), "r"(a2), "r"(0));
    asm("cvt.pack.sat.s8.s32.b32 %0, %1, %2, %3;" : "=r"(pk) : "r"(a1), "r"(a0), "r"(t));
    return pk;
}

// ---------------- kernel 1: merged prep ----------------
__global__ void prep_all(const float* __restrict__ x, const float* __restrict__ p,
                         const float* __restrict__ n) {
    int b = blockIdx.x;
    int t = threadIdx.x;
    int w = t >> 5, l = t & 31;
    __shared__ float s0[8], s1[8], s2[8];

    if (b < M_ROWS) {
        int row = b;
        const float4 xv = ((const float4*)(x + (size_t)row * DIM))[t];
        const float4 pv = ((const float4*)(p + (size_t)row * DIM))[t];
        ((uint32_t*)(g_Xq + (size_t)row * DIM))[t] = pack_s8x4(xv.x, xv.y, xv.z, xv.w);

        float sx = xv.x * xv.x + xv.y * xv.y + xv.z * xv.z + xv.w * xv.w;
        float sp = pv.x * pv.x + pv.y * pv.y + pv.z * pv.z + pv.w * pv.w;
        float dp = xv.x * pv.x + xv.y * pv.y + xv.z * pv.z + xv.w * pv.w;
        #pragma unroll
        for (int o = 16; o > 0; o >>= 1) {
            sx += __shfl_down_sync(0xffffffffu, sx, o);
            sp += __shfl_down_sync(0xffffffffu, sp, o);
            dp += __shfl_down_sync(0xffffffffu, dp, o);
        }
        if (l == 0) { s0[w] = sx; s1[w] = sp; s2[w] = dp; }
        __syncthreads();
        if (t == 0) {
            float ax = 0.f, ap = 0.f, ad = 0.f;
            #pragma unroll
            for (int i = 0; i < 8; i++) { ax += s0[i]; ap += s1[i]; ad += s2[i]; }
            float nx = sqrtf(ax), np = sqrtf(ap);
            g_rnx[row] = 1.0f / (QSCALE * QSCALE * nx);
            g_sim[row] = ad / fmaxf(nx * np, EPSF);
        }
    } else {
        int row = b - M_ROWS;
        const float4 nv = ((const float4*)(n + (size_t)row * DIM))[t];
        ((uint32_t*)(g_Nq + (size_t)row * DIM))[t] = pack_s8x4(nv.x, nv.y, nv.z, nv.w);

        float sn = nv.x * nv.x + nv.y * nv.y + nv.z * nv.z + nv.w * nv.w;
        #pragma unroll
        for (int o = 16; o > 0; o >>= 1) sn += __shfl_down_sync(0xffffffffu, sn, o);
        if (l == 0) s0[w] = sn;
        __syncthreads();
        if (t == 0) {
            float a = 0.f;
            #pragma unroll
            for (int i = 0; i < 8; i++) a += s0[i];
            g_rnn[row] = rsqrtf(a);
        }
    }
}

// ---------------- kernel 2: fused INT8 GEMM (s32 acc) + exp-rowsum epilogue ----------------
__global__ void __launch_bounds__(256, 2) gemm_fused() {
    extern __shared__ uint8_t dsm[];
    __shared__ float epi[128][4];
    __shared__ float s_rnn[BN];

    const int tid = threadIdx.x;
    const int mBase = blockIdx.y * BM;
    const int nBase = blockIdx.x * BN;

    if (tid < BN) s_rnn[tid] = g_rnn[nBase + tid];

    const int crow = tid >> 2;                  // 0..63
    const int cchk = (tid & 3) * 16;
    const uint8_t* srcA0 = g_Xq + (size_t)(mBase + crow) * DIM + (tid & 3) * 16;
    const uint8_t* srcB0 = g_Nq + (size_t)(nBase + crow) * DIM + (tid & 3) * 16;

    const int warp = tid >> 5, lane = tid & 31;
    const int warpM = warp >> 2;                // 0..1  (64 rows)
    const int warpN = warp & 3;                 // 0..3  (32 cols)
    const int g = lane >> 2, tg = lane & 3;

    // s32 accumulators: 4 m-frags x 4 n-frags x 4 regs
    int acc[4][4][4];
    #pragma unroll
    for (int mi = 0; mi < 4; mi++)
        #pragma unroll
        for (int ni = 0; ni < 4; ni++)
            #pragma unroll
            for (int q = 0; q < 4; q++) acc[mi][ni][q] = 0;

    const int aRow = warpM * 64 + (lane & 15);
    const int aCol = (lane >> 4) << 4;               // 0 / 16
    const int bRow = warpN * 32 + (lane & 7) + ((lane >> 4) << 3);
    const int bCol = ((lane >> 3) & 1) << 4;         // 0 / 16

    auto load_stage = [&](int s, int k0) {
        const uint32_t aoff = smem_u32(dsm) + s * STAGE;
        const uint32_t boff = aoff + A_STAGE;
        #pragma unroll
        for (int it = 0; it < 2; it++) {             // A: 128 rows x 4 chunks
            int r = crow + it * 64;
            asm volatile("cp.async.cg.shared.global [%0], [%1], 16;\n"
                         :: "r"(aoff + r * LDB + cchk),
                            "l"((const void*)(srcA0 + (size_t)it * 64 * DIM + k0)));
        }
        #pragma unroll
        for (int it = 0; it < 2; it++) {             // B: 128 rows x 4 chunks
            int r = crow + it * 64;
            asm volatile("cp.async.cg.shared.global [%0], [%1], 16;\n"
                         :: "r"(boff + r * LDB + cchk),
                            "l"((const void*)(srcB0 + (size_t)it * 64 * DIM + k0)));
        }
        asm volatile("cp.async.commit_group;\n" ::);
    };

    load_stage(0, 0);
    load_stage(1, BK);

    for (int t = 0; t < NK; t++) {
        asm volatile("cp.async.wait_group 1;\n" ::);
        __syncthreads();
        if (t + 2 < NK) load_stage((t + 2) % NSTAGE, (t + 2) * BK);

        const uint32_t aoff = smem_u32(dsm) + (t % NSTAGE) * STAGE;
        const uint32_t boff = aoff + A_STAGE;
        #pragma unroll
        for (int kk = 0; kk < BK; kk += 32) {
            uint32_t ar[4][4];
            #pragma unroll
            for (int mi = 0; mi < 4; mi++) {
                uint32_t addr = aoff + (aRow + mi * 16) * LDB + kk + aCol;
                asm volatile("ldmatrix.sync.aligned.m8n8.x4.shared.b16 {%0,%1,%2,%3}, [%4];\n"
                             : "=r"(ar[mi][0]), "=r"(ar[mi][1]), "=r"(ar[mi][2]), "=r"(ar[mi][3])
                             : "r"(addr));
            }
            #pragma unroll
            for (int nb = 0; nb < 2; nb++) {
                uint32_t addr = boff + (bRow + nb * 16) * LDB + kk + bCol;
                uint32_t r0, r1, r2, r3;
                asm volatile("ldmatrix.sync.aligned.m8n8.x4.shared.b16 {%0,%1,%2,%3}, [%4];\n"
                             : "=r"(r0), "=r"(r1), "=r"(r2), "=r"(r3) : "r"(addr));
                #pragma unroll
                for (int mi = 0; mi < 4; mi++) {
                    int* d0 = acc[mi][2 * nb];
                    asm volatile(
                        "mma.sync.aligned.m16n8k32.row.col.s32.s8.s8.s32 "
                        "{%0,%1,%2,%3}, {%4,%5,%6,%7}, {%8,%9}, {%0,%1,%2,%3};\n"
                        : "+r"(d0[0]), "+r"(d0[1]), "+r"(d0[2]), "+r"(d0[3])
                        : "r"(ar[mi][0]), "r"(ar[mi][1]), "r"(ar[mi][2]), "r"(ar[mi][3]),
                          "r"(r0), "r"(r1));
                    int* d1 = acc[mi][2 * nb + 1];
                    asm volatile(
                        "mma.sync.aligned.m16n8k32.row.col.s32.s8.s8.s32 "
                        "{%0,%1,%2,%3}, {%4,%5,%6,%7}, {%8,%9}, {%0,%1,%2,%3};\n"
                        : "+r"(d1[0]), "+r"(d1[1]), "+r"(d1[2]), "+r"(d1[3])
                        : "r"(ar[mi][0]), "r"(ar[mi][1]), "r"(ar[mi][2]), "r"(ar[mi][3]),
                          "r"(r2), "r"(r3));
                }
            }
        }
    }

    // ---- epilogue: exp(cos) + per-row sum over this block's 128 columns ----
    float rxv[4][2];
    #pragma unroll
    for (int mi = 0; mi < 4; mi++) {
        int r0 = mBase + warpM * 64 + mi * 16 + g;
        rxv[mi][0] = g_rnx[r0];         // includes 1/S^2
        rxv[mi][1] = g_rnx[r0 + 8];
    }

    float rs[4][2];
    #pragma unroll
    for (int mi = 0; mi < 4; mi++) { rs[mi][0] = 0.f; rs[mi][1] = 0.f; }

    #pragma unroll
    for (int ni = 0; ni < 4; ni++) {
        int c0 = warpN * 32 + ni * 8 + 2 * tg;
        float rn0 = s_rnn[c0], rn1 = s_rnn[c0 + 1];
        #pragma unroll
        for (int mi = 0; mi < 4; mi++) {
            const int* d = acc[mi][ni];
            rs[mi][0] += __expf(__int2float_rn(d[0]) * rxv[mi][0] * rn0)
                       + __expf(__int2float_rn(d[1]) * rxv[mi][0] * rn1);
            rs[mi][1] += __expf(__int2float_rn(d[2]) * rxv[mi][1] * rn0)
                       + __expf(__int2float_rn(d[3]) * rxv[mi][1] * rn1);
        }
    }

    #pragma unroll
    for (int mi = 0; mi < 4; mi++)
        #pragma unroll
        for (int h = 0; h < 2; h++) {
            float v = rs[mi][h];
            v += __shfl_xor_sync(0xffffffffu, v, 1);
            v += __shfl_xor_sync(0xffffffffu, v, 2);
            if (tg == 0) epi[warpM * 64 + mi * 16 + g + h * 8][warpN] = v;
        }
    __syncthreads();
    if (tid < 128) {
        float tot = (epi[tid][0] + epi[tid][1]) + (epi[tid][2] + epi[tid][3]);
        g_partial[(size_t)(mBase + tid) * NPART + blockIdx.x] = tot;
    }
}

// ---------------- kernel 3: per-row loss (warp per row) ----------------
__global__ void rowloss() {
    int row = (blockIdx.x * blockDim.x + threadIdx.x) >> 5;   // 0..4095
    int lane = threadIdx.x & 31;
    const float* p = g_partial + (size_t)row * NPART;
    float s = p[lane] + p[lane + 32];
    #pragma unroll
    for (int o = 16; o > 0; o >>= 1) s += __shfl_down_sync(0xffffffffu, s, o);
    if (lane == 0) g_rowloss[row] = logf(s) - g_sim[row];
}

// ---------------- kernel 4: final deterministic reduction ----------------
__global__ void reduce_loss(float* __restrict__ out) {
    int t = threadIdx.x;
    const float4* p4 = (const float4*)g_rowloss;
    float local = 0.f;
    #pragma unroll
    for (int i = 0; i < 4; i++) {
        float4 v = p4[t + i * 256];
        local += v.x + v.y + v.z + v.w;
    }
    #pragma unroll
    for (int o = 16; o > 0; o >>= 1) local += __shfl_down_sync(0xffffffffu, local, o);
    __shared__ float red[8];
    int w = t >> 5, l = t & 31;
    if (l == 0) red[w] = local;
    __syncthreads();
    if (t == 0) {
        float tot = 0.f;
        #pragma unroll
        for (int i = 0; i < 8; i++) tot += red[i];
        out[0] = tot * (1.0f / (float)M_ROWS);
    }
}

// ---------------- launch ----------------
extern "C" void kernel_launch(void* const* d_in, const int* in_sizes, int n_in,
                              void* d_out, int out_size) {
    const float* x   = (const float*)d_in[0];
    const float* pos = (const float*)d_in[1];
    const float* neg = (const float*)d_in[2];

    static bool attr_set = false;
    if (!attr_set) {
        cudaFuncSetAttribute(gemm_fused, cudaFuncAttributeMaxDynamicSharedMemorySize, DYN_SMEM);
        attr_set = true;
    }

    prep_all<<<M_ROWS + N_ROWS, 256>>>(x, pos, neg);
    dim3 grid(N_ROWS / BN, M_ROWS / BM);   // (64, 32)
    gemm_fused<<<grid, 256, DYN_SMEM>>>();
    rowloss<<<M_ROWS / 8, 256>>>();
    reduce_loss<<<1, 256>>>((float*)d_out);
}

// round 15
// speedup vs baseline: 2.5070x; 2.5070x over previous
#include <cuda_runtime.h>
#include <cuda_bf16.h>
#include <cuda_fp16.h>
#include <cstdint>

// Problem shape: x[4096,1024], positive[4096,1024], negative[8192,1024]
#define M_ROWS 4096
#define N_ROWS 8192
#define DIM    1024
#define EPSF   1e-8f

// GEMM tiling
#define BM 128
#define BN 256
#define BK 64
#define NK (DIM / BK)            // 16
#define NPART (N_ROWS / BN)      // 32 partials per row
#define LDB 80                   // padded smem row bytes: conflict-free ldmatrix
#define NSTAGE 3
#define A_STAGE (BM * LDB)       // 10240
#define B_STAGE (BN * LDB)       // 20480
#define STAGE (A_STAGE + B_STAGE) // 30720
#define DYN_SMEM (NSTAGE * STAGE) // 92160
#define RL_BLOCKS (M_ROWS / 8)   // 512 rowloss blocks

// ---------------- scratch (no allocations allowed) ----------------
__device__ uint8_t g_Xf8[(size_t)M_ROWS * DIM];   // 4 MB  e4m3
__device__ uint8_t g_Nf8[(size_t)N_ROWS * DIM];   // 8 MB  e4m3
__device__ float g_rnx[M_ROWS];                    // 1/norm(x)
__device__ float g_sim[M_ROWS];
__device__ float g_rnn[N_ROWS];                    // 1/norm(neg)
__device__ float g_partial[(size_t)M_ROWS * NPART];
__device__ float g_blocksum[RL_BLOCKS];

__device__ __forceinline__ uint32_t smem_u32(const void* p) {
    return (uint32_t)__cvta_generic_to_shared(p);
}

// pack 4 floats -> 4 e4m3 bytes (byte0 = v0)
__device__ __forceinline__ uint32_t pack_e4m3x4(float v0, float v1, float v2, float v3) {
    uint32_t pk;
    asm("{\n\t.reg .b16 lo, hi;\n\t"
        "cvt.rn.satfinite.e4m3x2.f32 lo, %2, %1;\n\t"
        "cvt.rn.satfinite.e4m3x2.f32 hi, %4, %3;\n\t"
        "mov.b32 %0, {lo, hi};\n\t}"
        : "=r"(pk) : "f"(v0), "f"(v1), "f"(v2), "f"(v3));
    return pk;
}

// ---------------- kernel 1: merged prep ----------------
__global__ void prep_all(const float* __restrict__ x, const float* __restrict__ p,
                         const float* __restrict__ n) {
    int b = blockIdx.x;
    int t = threadIdx.x;
    int w = t >> 5, l = t & 31;
    __shared__ float s0[8], s1[8], s2[8];

    if (b < M_ROWS) {
        int row = b;
        const float4 xv = ((const float4*)(x + (size_t)row * DIM))[t];
        const float4 pv = ((const float4*)(p + (size_t)row * DIM))[t];
        ((uint32_t*)(g_Xf8 + (size_t)row * DIM))[t] = pack_e4m3x4(xv.x, xv.y, xv.z, xv.w);

        float sx = xv.x * xv.x + xv.y * xv.y + xv.z * xv.z + xv.w * xv.w;
        float sp = pv.x * pv.x + pv.y * pv.y + pv.z * pv.z + pv.w * pv.w;
        float dp = xv.x * pv.x + xv.y * pv.y + xv.z * pv.z + xv.w * pv.w;
        #pragma unroll
        for (int o = 16; o > 0; o >>= 1) {
            sx += __shfl_down_sync(0xffffffffu, sx, o);
            sp += __shfl_down_sync(0xffffffffu, sp, o);
            dp += __shfl_down_sync(0xffffffffu, dp, o);
        }
        if (l == 0) { s0[w] = sx; s1[w] = sp; s2[w] = dp; }
        __syncthreads();
        if (t == 0) {
            float ax = 0.f, ap = 0.f, ad = 0.f;
            #pragma unroll
            for (int i = 0; i < 8; i++) { ax += s0[i]; ap += s1[i]; ad += s2[i]; }
            float nx = sqrtf(ax), np = sqrtf(ap);
            g_rnx[row] = 1.0f / nx;
            g_sim[row] = ad / fmaxf(nx * np, EPSF);
        }
    } else {
        int row = b - M_ROWS;
        const float4 nv = ((const float4*)(n + (size_t)row * DIM))[t];
        ((uint32_t*)(g_Nf8 + (size_t)row * DIM))[t] = pack_e4m3x4(nv.x, nv.y, nv.z, nv.w);

        float sn = nv.x * nv.x + nv.y * nv.y + nv.z * nv.z + nv.w * nv.w;
        #pragma unroll
        for (int o = 16; o > 0; o >>= 1) sn += __shfl_down_sync(0xffffffffu, sn, o);
        if (l == 0) s0[w] = sn;
        __syncthreads();
        if (t == 0) {
            float a = 0.f;
            #pragma unroll
            for (int i = 0; i < 8; i++) a += s0[i];
            g_rnn[row] = rsqrtf(a);
        }
    }
}

// ---------------- kernel 2: fused FP8 GEMM (f16 acc, 2x4 warp grid, 64x64 warp tile) ----------------
__global__ void __launch_bounds__(256, 2) gemm_fused() {
    extern __shared__ uint8_t dsm[];
    __shared__ float epi[128][4];
    __shared__ float s_rnn[BN];

    const int tid = threadIdx.x;
    const int mBase = blockIdx.y * BM;
    const int nBase = blockIdx.x * BN;

    s_rnn[tid] = g_rnn[nBase + tid];

    const int crow = tid >> 2;                  // 0..63
    const int cchk = (tid & 3) * 16;
    const uint8_t* srcA0 = g_Xf8 + (size_t)(mBase + crow) * DIM + (tid & 3) * 16;
    const uint8_t* srcB0 = g_Nf8 + (size_t)(nBase + crow) * DIM + (tid & 3) * 16;

    const int warp = tid >> 5, lane = tid & 31;
    const int warpM = warp >> 2;                // 0..1  (64 rows each)
    const int warpN = warp & 3;                 // 0..3  (64 cols each)
    const int g = lane >> 2, tg = lane & 3;

    // f16 accumulators: 4 m-frags x 8 n-frags x 2 b32
    uint32_t acc[4][8][2];
    #pragma unroll
    for (int mi = 0; mi < 4; mi++)
        #pragma unroll
        for (int ni = 0; ni < 8; ni++) { acc[mi][ni][0] = 0u; acc[mi][ni][1] = 0u; }

    const int aRow = warpM * 64 + (lane & 15);
    const int aCol = (lane >> 4) << 4;               // 0 / 16
    const int bRow = warpN * 64 + (lane & 7) + ((lane >> 4) << 3);
    const int bCol = ((lane >> 3) & 1) << 4;         // 0 / 16

    auto load_stage = [&](int s, int k0) {
        const uint32_t aoff = smem_u32(dsm) + s * STAGE;
        const uint32_t boff = aoff + A_STAGE;
        #pragma unroll
        for (int it = 0; it < 2; it++) {             // A: 128 rows
            int r = crow + it * 64;
            asm volatile("cp.async.cg.shared.global [%0], [%1], 16;\n"
                         :: "r"(aoff + r * LDB + cchk),
                            "l"((const void*)(srcA0 + (size_t)it * 64 * DIM + k0)));
        }
        #pragma unroll
        for (int it = 0; it < 4; it++) {             // B: 256 rows
            int r = crow + it * 64;
            asm volatile("cp.async.cg.shared.global [%0], [%1], 16;\n"
                         :: "r"(boff + r * LDB + cchk),
                            "l"((const void*)(srcB0 + (size_t)it * 64 * DIM + k0)));
        }
        asm volatile("cp.async.commit_group;\n" ::);
    };

    load_stage(0, 0);
    load_stage(1, BK);

    for (int t = 0; t < NK; t++) {
        asm volatile("cp.async.wait_group 1;\n" ::);
        __syncthreads();
        if (t + 2 < NK) load_stage((t + 2) % NSTAGE, (t + 2) * BK);

        const uint32_t aoff = smem_u32(dsm) + (t % NSTAGE) * STAGE;
        const uint32_t boff = aoff + A_STAGE;
        #pragma unroll
        for (int kk = 0; kk < BK; kk += 32) {
            uint32_t ar[4][4];
            #pragma unroll
            for (int mi = 0; mi < 4; mi++) {
                uint32_t addr = aoff + (aRow + mi * 16) * LDB + kk + aCol;
                asm volatile("ldmatrix.sync.aligned.m8n8.x4.shared.b16 {%0,%1,%2,%3}, [%4];\n"
                             : "=r"(ar[mi][0]), "=r"(ar[mi][1]), "=r"(ar[mi][2]), "=r"(ar[mi][3])
                             : "r"(addr));
            }
            #pragma unroll
            for (int nb = 0; nb < 4; nb++) {
                uint32_t addr = boff + (bRow + nb * 16) * LDB + kk + bCol;
                uint32_t r0, r1, r2, r3;
                asm volatile("ldmatrix.sync.aligned.m8n8.x4.shared.b16 {%0,%1,%2,%3}, [%4];\n"
                             : "=r"(r0), "=r"(r1), "=r"(r2), "=r"(r3) : "r"(addr));
                #pragma unroll
                for (int mi = 0; mi < 4; mi++) {
                    uint32_t* d0 = acc[mi][2 * nb];
                    asm volatile(
                        "mma.sync.aligned.m16n8k32.row.col.f16.e4m3.e4m3.f16 "
                        "{%0,%1}, {%2,%3,%4,%5}, {%6,%7}, {%0,%1};\n"
                        : "+r"(d0[0]), "+r"(d0[1])
                        : "r"(ar[mi][0]), "r"(ar[mi][1]), "r"(ar[mi][2]), "r"(ar[mi][3]),
                          "r"(r0), "r"(r1));
                    uint32_t* d1 = acc[mi][2 * nb + 1];
                    asm volatile(
                        "mma.sync.aligned.m16n8k32.row.col.f16.e4m3.e4m3.f16 "
                        "{%0,%1}, {%2,%3,%4,%5}, {%6,%7}, {%0,%1};\n"
                        : "+r"(d1[0]), "+r"(d1[1])
                        : "r"(ar[mi][0]), "r"(ar[mi][1]), "r"(ar[mi][2]), "r"(ar[mi][3]),
                          "r"(r2), "r"(r3));
                }
            }
        }
    }

    // ---- epilogue: exp(cos) + per-row sum over this block's 256 columns ----
    float rxv[4][2];
    #pragma unroll
    for (int mi = 0; mi < 4; mi++) {
        int r0 = mBase + warpM * 64 + mi * 16 + g;
        rxv[mi][0] = g_rnx[r0];
        rxv[mi][1] = g_rnx[r0 + 8];
    }

    float rs[4][2];
    #pragma unroll
    for (int mi = 0; mi < 4; mi++) { rs[mi][0] = 0.f; rs[mi][1] = 0.f; }

    #pragma unroll
    for (int ni = 0; ni < 8; ni++) {
        int c0 = warpN * 64 + ni * 8 + 2 * tg;
        float rn0 = s_rnn[c0], rn1 = s_rnn[c0 + 1];
        #pragma unroll
        for (int mi = 0; mi < 4; mi++) {
            float2 lo = __half22float2(*(const __half2*)&acc[mi][ni][0]);  // row g
            float2 hi = __half22float2(*(const __half2*)&acc[mi][ni][1]);  // row g+8
            rs[mi][0] += __expf(lo.x * rxv[mi][0] * rn0)
                       + __expf(lo.y * rxv[mi][0] * rn1);
            rs[mi][1] += __expf(hi.x * rxv[mi][1] * rn0)
                       + __expf(hi.y * rxv[mi][1] * rn1);
        }
    }

    #pragma unroll
    for (int mi = 0; mi < 4; mi++)
        #pragma unroll
        for (int h = 0; h < 2; h++) {
            float v = rs[mi][h];
            v += __shfl_xor_sync(0xffffffffu, v, 1);
            v += __shfl_xor_sync(0xffffffffu, v, 2);
            if (tg == 0) epi[warpM * 64 + mi * 16 + g + h * 8][warpN] = v;
        }
    __syncthreads();
    if (tid < 128) {
        float tot = (epi[tid][0] + epi[tid][1]) + (epi[tid][2] + epi[tid][3]);
        g_partial[(size_t)(mBase + tid) * NPART + blockIdx.x] = tot;
    }
}

// ---------------- kernel 3: per-row loss + per-block partial (8 rows/block) ----------------
__global__ void rowloss() {
    int row = (blockIdx.x * blockDim.x + threadIdx.x) >> 5;   // 0..4095
    int warp = threadIdx.x >> 5;                              // 0..7
    int lane = threadIdx.x & 31;
    float s = g_partial[(size_t)row * NPART + lane];
    #pragma unroll
    for (int o = 16; o > 0; o >>= 1) s += __shfl_down_sync(0xffffffffu, s, o);
    __shared__ float sl[8];
    if (lane == 0) sl[warp] = logf(s) - g_sim[row];
    __syncthreads();
    if (threadIdx.x == 0) {
        float b = 0.f;
        #pragma unroll
        for (int i = 0; i < 8; i++) b += sl[i];
        g_blocksum[blockIdx.x] = b;
    }
}

// ---------------- kernel 4: final deterministic reduction (512 values) ----------------
__global__ void reduce_loss(float* __restrict__ out) {
    int t = threadIdx.x;                 // 128 threads
    const float4* p4 = (const float4*)g_blocksum;
    float4 v = p4[t];                    // 128 x 4 = 512
    float local = (v.x + v.y) + (v.z + v.w);
    #pragma unroll
    for (int o = 16; o > 0; o >>= 1) local += __shfl_down_sync(0xffffffffu, local, o);
    __shared__ float red[4];
    int w = t >> 5, l = t & 31;
    if (l == 0) red[w] = local;
    __syncthreads();
    if (t == 0) {
        float tot = (red[0] + red[1]) + (red[2] + red[3]);
        out[0] = tot * (1.0f / (float)M_ROWS);
    }
}

// ---------------- launch ----------------
extern "C" void kernel_launch(void* const* d_in, const int* in_sizes, int n_in,
                              void* d_out, int out_size) {
    const float* x   = (const float*)d_in[0];
    const float* pos = (const float*)d_in[1];
    const float* neg = (const float*)d_in[2];

    static bool attr_set = false;
    if (!attr_set) {
        cudaFuncSetAttribute(gemm_fused, cudaFuncAttributeMaxDynamicSharedMemorySize, DYN_SMEM);
        attr_set = true;
    }

    prep_all<<<M_ROWS + N_ROWS, 256>>>(x, pos, neg);
    dim3 grid(N_ROWS / BN, M_ROWS / BM);   // (32, 32)
    gemm_fused<<<grid, 256, DYN_SMEM>>>();
    rowloss<<<RL_BLOCKS, 256>>>();
    reduce_loss<<<1, 128>>>((float*)d_out);
}

// round 17
// speedup vs baseline: 2.5266x; 1.0078x over previous
#include <cuda_runtime.h>
#include <cuda_bf16.h>
#include <cuda_fp16.h>
#include <cstdint>

// Problem shape: x[4096,1024], positive[4096,1024], negative[8192,1024]
#define M_ROWS 4096
#define N_ROWS 8192
#define DIM    1024
#define EPSF   1e-8f

// GEMM tiling
#define BM 128
#define BN 256
#define BK 64
#define NK (DIM / BK)            // 16
#define NPART (N_ROWS / BN)      // 32 partials per row
#define LDB 80                   // padded smem row bytes: conflict-free ldmatrix
#define NSTAGE 3
#define A_STAGE (BM * LDB)       // 10240
#define B_STAGE (BN * LDB)       // 20480
#define STAGE (A_STAGE + B_STAGE) // 30720
#define DYN_SMEM (NSTAGE * STAGE) // 92160
#define RL_BLOCKS (M_ROWS / 8)   // 512 rowloss blocks

// ---------------- scratch (no allocations allowed) ----------------
__device__ uint8_t g_Xf8[(size_t)M_ROWS * DIM];   // 4 MB  e4m3
__device__ uint8_t g_Nf8[(size_t)N_ROWS * DIM];   // 8 MB  e4m3
__device__ float g_rnx[M_ROWS];                    // 1/norm(x)
__device__ float g_sim[M_ROWS];
__device__ float g_rnn[N_ROWS];                    // 1/norm(neg)
__device__ float g_partial[(size_t)M_ROWS * NPART];
__device__ float g_blocksum[RL_BLOCKS];
__device__ unsigned int g_ticket = 0;

__device__ __forceinline__ uint32_t smem_u32(const void* p) {
    return (uint32_t)__cvta_generic_to_shared(p);
}

// pack 4 floats -> 4 e4m3 bytes (byte0 = v0)
__device__ __forceinline__ uint32_t pack_e4m3x4(float v0, float v1, float v2, float v3) {
    uint32_t pk;
    asm("{\n\t.reg .b16 lo, hi;\n\t"
        "cvt.rn.satfinite.e4m3x2.f32 lo, %2, %1;\n\t"
        "cvt.rn.satfinite.e4m3x2.f32 hi, %4, %3;\n\t"
        "mov.b32 %0, {lo, hi};\n\t}"
        : "=r"(pk) : "f"(v0), "f"(v1), "f"(v2), "f"(v3));
    return pk;
}

// ---------------- kernel 1: merged prep ----------------
__global__ void prep_all(const float* __restrict__ x, const float* __restrict__ p,
                         const float* __restrict__ n) {
    int b = blockIdx.x;
    int t = threadIdx.x;
    int w = t >> 5, l = t & 31;
    __shared__ float s0[8], s1[8], s2[8];

    if (b < M_ROWS) {
        int row = b;
        const float4 xv = ((const float4*)(x + (size_t)row * DIM))[t];
        const float4 pv = ((const float4*)(p + (size_t)row * DIM))[t];
        ((uint32_t*)(g_Xf8 + (size_t)row * DIM))[t] = pack_e4m3x4(xv.x, xv.y, xv.z, xv.w);

        float sx = xv.x * xv.x + xv.y * xv.y + xv.z * xv.z + xv.w * xv.w;
        float sp = pv.x * pv.x + pv.y * pv.y + pv.z * pv.z + pv.w * pv.w;
        float dp = xv.x * pv.x + xv.y * pv.y + xv.z * pv.z + xv.w * pv.w;
        #pragma unroll
        for (int o = 16; o > 0; o >>= 1) {
            sx += __shfl_down_sync(0xffffffffu, sx, o);
            sp += __shfl_down_sync(0xffffffffu, sp, o);
            dp += __shfl_down_sync(0xffffffffu, dp, o);
        }
        if (l == 0) { s0[w] = sx; s1[w] = sp; s2[w] = dp; }
        __syncthreads();
        if (t == 0) {
            float ax = 0.f, ap = 0.f, ad = 0.f;
            #pragma unroll
            for (int i = 0; i < 8; i++) { ax += s0[i]; ap += s1[i]; ad += s2[i]; }
            float nx = sqrtf(ax), np = sqrtf(ap);
            g_rnx[row] = 1.0f / nx;
            g_sim[row] = ad / fmaxf(nx * np, EPSF);
        }
    } else {
        int row = b - M_ROWS;
        const float4 nv = ((const float4*)(n + (size_t)row * DIM))[t];
        ((uint32_t*)(g_Nf8 + (size_t)row * DIM))[t] = pack_e4m3x4(nv.x, nv.y, nv.z, nv.w);

        float sn = nv.x * nv.x + nv.y * nv.y + nv.z * nv.z + nv.w * nv.w;
        #pragma unroll
        for (int o = 16; o > 0; o >>= 1) sn += __shfl_down_sync(0xffffffffu, sn, o);
        if (l == 0) s0[w] = sn;
        __syncthreads();
        if (t == 0) {
            float a = 0.f;
            #pragma unroll
            for (int i = 0; i < 8; i++) a += s0[i];
            g_rnn[row] = rsqrtf(a);
        }
    }
}

// ---------------- kernel 2: fused FP8 GEMM (f16 acc, 2x4 warp grid, 64x64 warp tile) ----------------
__global__ void __launch_bounds__(256, 2) gemm_fused() {
    extern __shared__ uint8_t dsm[];
    __shared__ float epi[128][4];
    __shared__ float s_rnn[BN];

    const int tid = threadIdx.x;
    const int mBase = blockIdx.y * BM;
    const int nBase = blockIdx.x * BN;

    const int crow = tid >> 2;                  // 0..63
    const int cchk = (tid & 3) * 16;
    const uint8_t* srcA0 = g_Xf8 + (size_t)(mBase + crow) * DIM + (tid & 3) * 16;
    const uint8_t* srcB0 = g_Nf8 + (size_t)(nBase + crow) * DIM + (tid & 3) * 16;

    const int warp = tid >> 5, lane = tid & 31;
    const int warpM = warp >> 2;                // 0..1  (64 rows each)
    const int warpN = warp & 3;                 // 0..3  (64 cols each)
    const int g = lane >> 2, tg = lane & 3;

    // f16 accumulators: 4 m-frags x 8 n-frags x 2 b32
    uint32_t acc[4][8][2];
    #pragma unroll
    for (int mi = 0; mi < 4; mi++)
        #pragma unroll
        for (int ni = 0; ni < 8; ni++) { acc[mi][ni][0] = 0u; acc[mi][ni][1] = 0u; }

    const int aRow = warpM * 64 + (lane & 15);
    const int aCol = (lane >> 4) << 4;               // 0 / 16
    const int bRow = warpN * 64 + (lane & 7) + ((lane >> 4) << 3);
    const int bCol = ((lane >> 3) & 1) << 4;         // 0 / 16

    auto load_stage = [&](int s, int k0) {
        const uint32_t aoff = smem_u32(dsm) + s * STAGE;
        const uint32_t boff = aoff + A_STAGE;
        #pragma unroll
        for (int it = 0; it < 2; it++) {             // A: 128 rows
            int r = crow + it * 64;
            asm volatile("cp.async.cg.shared.global [%0], [%1], 16;\n"
                         :: "r"(aoff + r * LDB + cchk),
                            "l"((const void*)(srcA0 + (size_t)it * 64 * DIM + k0)));
        }
        #pragma unroll
        for (int it = 0; it < 4; it++) {             // B: 256 rows
            int r = crow + it * 64;
            asm volatile("cp.async.cg.shared.global [%0], [%1], 16;\n"
                         :: "r"(boff + r * LDB + cchk),
                            "l"((const void*)(srcB0 + (size_t)it * 64 * DIM + k0)));
        }
        asm volatile("cp.async.commit_group;\n" ::);
    };

    load_stage(0, 0);
    s_rnn[tid] = g_rnn[nBase + tid];
    load_stage(1, BK);

    for (int t = 0; t < NK; t++) {
        asm volatile("cp.async.wait_group 1;\n" ::);
        __syncthreads();
        if (t + 2 < NK) load_stage((t + 2) % NSTAGE, (t + 2) * BK);

        const uint32_t aoff = smem_u32(dsm) + (t % NSTAGE) * STAGE;
        const uint32_t boff = aoff + A_STAGE;
        #pragma unroll
        for (int kk = 0; kk < BK; kk += 32) {
            uint32_t ar[4][4];
            #pragma unroll
            for (int mi = 0; mi < 4; mi++) {
                uint32_t addr = aoff + (aRow + mi * 16) * LDB + kk + aCol;
                asm volatile("ldmatrix.sync.aligned.m8n8.x4.shared.b16 {%0,%1,%2,%3}, [%4];\n"
                             : "=r"(ar[mi][0]), "=r"(ar[mi][1]), "=r"(ar[mi][2]), "=r"(ar[mi][3])
                             : "r"(addr));
            }
            #pragma unroll
            for (int nb = 0; nb < 4; nb++) {
                uint32_t addr = boff + (bRow + nb * 16) * LDB + kk + bCol;
                uint32_t r0, r1, r2, r3;
                asm volatile("ldmatrix.sync.aligned.m8n8.x4.shared.b16 {%0,%1,%2,%3}, [%4];\n"
                             : "=r"(r0), "=r"(r1), "=r"(r2), "=r"(r3) : "r"(addr));
                #pragma unroll
                for (int mi = 0; mi < 4; mi++) {
                    uint32_t* d0 = acc[mi][2 * nb];
                    asm volatile(
                        "mma.sync.aligned.m16n8k32.row.col.f16.e4m3.e4m3.f16 "
                        "{%0,%1}, {%2,%3,%4,%5}, {%6,%7}, {%0,%1};\n"
                        : "+r"(d0[0]), "+r"(d0[1])
                        : "r"(ar[mi][0]), "r"(ar[mi][1]), "r"(ar[mi][2]), "r"(ar[mi][3]),
                          "r"(r0), "r"(r1));
                    uint32_t* d1 = acc[mi][2 * nb + 1];
                    asm volatile(
                        "mma.sync.aligned.m16n8k32.row.col.f16.e4m3.e4m3.f16 "
                        "{%0,%1}, {%2,%3,%4,%5}, {%6,%7}, {%0,%1};\n"
                        : "+r"(d1[0]), "+r"(d1[1])
                        : "r"(ar[mi][0]), "r"(ar[mi][1]), "r"(ar[mi][2]), "r"(ar[mi][3]),
                          "r"(r2), "r"(r3));
                }
            }
        }
    }

    // ---- epilogue: exp(cos) + per-row sum over this block's 256 columns ----
    float rxv[4][2];
    #pragma unroll
    for (int mi = 0; mi < 4; mi++) {
        int r0 = mBase + warpM * 64 + mi * 16 + g;
        rxv[mi][0] = g_rnx[r0];
        rxv[mi][1] = g_rnx[r0 + 8];
    }

    float rs[4][2];
    #pragma unroll
    for (int mi = 0; mi < 4; mi++) { rs[mi][0] = 0.f; rs[mi][1] = 0.f; }

    #pragma unroll
    for (int ni = 0; ni < 8; ni++) {
        int c0 = warpN * 64 + ni * 8 + 2 * tg;
        float rn0 = s_rnn[c0], rn1 = s_rnn[c0 + 1];
        #pragma unroll
        for (int mi = 0; mi < 4; mi++) {
            float2 lo = __half22float2(*(const __half2*)&acc[mi][ni][0]);  // row g
            float2 hi = __half22float2(*(const __half2*)&acc[mi][ni][1]);  // row g+8
            rs[mi][0] += __expf(lo.x * rxv[mi][0] * rn0)
                       + __expf(lo.y * rxv[mi][0] * rn1);
            rs[mi][1] += __expf(hi.x * rxv[mi][1] * rn0)
                       + __expf(hi.y * rxv[mi][1] * rn1);
        }
    }

    #pragma unroll
    for (int mi = 0; mi < 4; mi++)
        #pragma unroll
        for (int h = 0; h < 2; h++) {
            float v = rs[mi][h];
            v += __shfl_xor_sync(0xffffffffu, v, 1);
            v += __shfl_xor_sync(0xffffffffu, v, 2);
            if (tg == 0) epi[warpM * 64 + mi * 16 + g + h * 8][warpN] = v;
        }
    __syncthreads();
    if (tid < 128) {
        float tot = (epi[tid][0] + epi[tid][1]) + (epi[tid][2] + epi[tid][3]);
        g_partial[(size_t)(mBase + tid) * NPART + blockIdx.x] = tot;
    }
}

// ---------------- kernel 3: per-row loss + deterministic last-block final reduce ----------------
__global__ void rowloss_final(float* __restrict__ out) {
    int row = (blockIdx.x * blockDim.x + threadIdx.x) >> 5;   // 0..4095
    int warp = threadIdx.x >> 5;                              // 0..7
    int lane = threadIdx.x & 31;
    float s = g_partial[(size_t)row * NPART + lane];
    #pragma unroll
    for (int o = 16; o > 0; o >>= 1) s += __shfl_down_sync(0xffffffffu, s, o);
    __shared__ float sl[8];
    __shared__ bool is_last;
    if (lane == 0) sl[warp] = logf(s) - g_sim[row];
    __syncthreads();
    if (threadIdx.x == 0) {
        float b = 0.f;
        #pragma unroll
        for (int i = 0; i < 8; i++) b += sl[i];
        g_blocksum[blockIdx.x] = b;
        __threadfence();
        unsigned int tk = atomicAdd(&g_ticket, 1u);
        is_last = (tk == RL_BLOCKS - 1);
    }
    __syncthreads();

    if (is_last) {
        // final reduce of 512 partials (deterministic order), 256 threads
        int t = threadIdx.x;
        float v = g_blocksum[t] + g_blocksum[t + 256];
        #pragma unroll
        for (int o = 16; o > 0; o >>= 1) v += __shfl_down_sync(0xffffffffu, v, o);
        __shared__ float red[8];
        if (lane == 0) red[warp] = v;
        __syncthreads();
        if (t == 0) {
            float tot = 0.f;
            #pragma unroll
            for (int i = 0; i < 8; i++) tot += red[i];
            out[0] = tot * (1.0f / (float)M_ROWS);
            g_ticket = 0;             // reset for next graph replay
        }
    }
}

// ---------------- launch ----------------
extern "C" void kernel_launch(void* const* d_in, const int* in_sizes, int n_in,
                              void* d_out, int out_size) {
    const float* x   = (const float*)d_in[0];
    const float* pos = (const float*)d_in[1];
    const float* neg = (const float*)d_in[2];

    static bool attr_set = false;
    if (!attr_set) {
        cudaFuncSetAttribute(gemm_fused, cudaFuncAttributeMaxDynamicSharedMemorySize, DYN_SMEM);
        attr_set = true;
    }

    prep_all<<<M_ROWS + N_ROWS, 256>>>(x, pos, neg);
    dim3 grid(N_ROWS / BN, M_ROWS / BM);   // (32, 32)
    gemm_fused<<<grid, 256, DYN_SMEM>>>();
    rowloss_final<<<RL_BLOCKS, 256>>>((float*)d_out);
}